// round 16
// baseline (speedup 1.0000x reference)
#include <cuda_runtime.h>
#include <cuda_fp16.h>

#define TSTEPS 2048
#define HID    2048
#define INP    1024
#define NOUT   512
#define ZLEN   (HID + INP)
#define NCTA   147
#define JPER   14
#define GSTRIDE (NCTA * 56)                  /* 8232 floats per timestep */
#define SWS    2056                          /* padded row stride (halfs): conflict-free ldmatrix */
#define FSTRIDE 64                           /* flag spacing: 64 u32 = 256B */

#define SRED_OFF   (56 * SWS * 2)            /* 230272 : sRed[8][64] f32 */
#define SMEM_TOTAL (SRED_OFF + 2048)         /* 232320 <= 232448 */

__device__ __align__(256) float  d_G2[(size_t)TSTEPS * GSTRIDE];
__device__ __align__(256) __half d_h16[(size_t)TSTEPS * HID];   /* h history, fp16, PERMUTED */
__device__ __align__(256) unsigned d_flags[NCTA * FSTRIDE];

__device__ __forceinline__ unsigned packh2(float a, float b) {
    __half2 h = __floats2half2_rn(a, b);
    return *(unsigned*)&h;
}
__device__ __forceinline__ float sigmoidf_(float x) { return 1.0f / (1.0f + __expf(-x)); }
__device__ __forceinline__ float tanhf_(float x) {
    float e = __expf(2.0f * x); return 1.0f - 2.0f / (e + 1.0f);
}
__device__ __forceinline__ void ldmx4(unsigned &r0, unsigned &r1, unsigned &r2, unsigned &r3,
                                      unsigned addr) {
    asm volatile("ldmatrix.sync.aligned.m8n8.x4.shared.b16 {%0,%1,%2,%3}, [%4];"
                 : "=r"(r0), "=r"(r1), "=r"(r2), "=r"(r3) : "r"(addr));
}
__device__ __forceinline__ void mma16816(float &c0, float &c1, float &c2, float &c3,
                                         unsigned a0, unsigned a1, unsigned a2, unsigned a3,
                                         unsigned b0, unsigned b1) {
    asm volatile("mma.sync.aligned.m16n8k16.row.col.f32.f16.f16.f32 "
                 "{%0,%1,%2,%3}, {%4,%5,%6,%7}, {%8,%9}, {%0,%1,%2,%3};"
                 : "+f"(c0), "+f"(c1), "+f"(c2), "+f"(c3)
                 : "r"(a0), "r"(a1), "r"(a2), "r"(a3), "r"(b0), "r"(b1));
}

// h-exchange permutation within a 256-half slice (see R15 derivation).
__device__ __forceinline__ int hperm(int i) {
    return 4 * ((i & 7) + 8 * (i >> 5)) + ((i >> 3) & 3);
}

// ---------------- GEMM: x-part preactivations, transposed output layout -------
__global__ __launch_bounds__(256) void gemm_xpart(
    const float* __restrict__ Wf, const float* __restrict__ Wi,
    const float* __restrict__ Wc, const float* __restrict__ Wo,
    const float* __restrict__ bf, const float* __restrict__ bi,
    const float* __restrict__ bc, const float* __restrict__ bo,
    const float* __restrict__ X)
{
    __shared__ float As[16][132];
    __shared__ float Bs[16][132];
    const int bx = blockIdx.x, by = blockIdx.y;
    const int g = by >> 4, jb2 = (by & 15) << 7;
    const float* W  = (g == 0) ? Wf : (g == 1) ? Wi : (g == 2) ? Wc : Wo;
    const float* bb = (g == 0) ? bf : (g == 1) ? bi : (g == 2) ? bc : bo;
    const int tid = threadIdx.x, tx = tid & 15, ty = tid >> 4;
    float acc[8][8];
#pragma unroll
    for (int i = 0; i < 8; ++i)
#pragma unroll
        for (int j = 0; j < 8; ++j) acc[i][j] = 0.0f;
    for (int k0 = 0; k0 < INP; k0 += 16) {
#pragma unroll
        for (int i = 0; i < 2; ++i) {
            int f = tid + i * 256, row = f >> 2, kk = (f & 3) << 2;
            float4 v = *(const float4*)(W + (size_t)(jb2 + row) * ZLEN + HID + k0 + kk);
            As[kk][row] = v.x; As[kk+1][row] = v.y; As[kk+2][row] = v.z; As[kk+3][row] = v.w;
            float4 u = *(const float4*)(X + (size_t)((bx << 7) + row) * INP + k0 + kk);
            Bs[kk][row] = u.x; Bs[kk+1][row] = u.y; Bs[kk+2][row] = u.z; Bs[kk+3][row] = u.w;
        }
        __syncthreads();
#pragma unroll
        for (int k = 0; k < 16; ++k) {
            float a[8], b[8];
            *(float4*)&a[0] = *(const float4*)&As[k][ty*8];
            *(float4*)&a[4] = *(const float4*)&As[k][ty*8+4];
            *(float4*)&b[0] = *(const float4*)&Bs[k][tx*8];
            *(float4*)&b[4] = *(const float4*)&Bs[k][tx*8+4];
#pragma unroll
            for (int ii = 0; ii < 8; ++ii)
#pragma unroll
                for (int jj = 0; jj < 8; ++jj)
                    acc[ii][jj] = fmaf(a[ii], b[jj], acc[ii][jj]);
        }
        __syncthreads();
    }
#pragma unroll
    for (int ii = 0; ii < 8; ++ii) {
        const int j = jb2 + ty * 8 + ii;
        const float bv = __ldg(bb + j);
        const int bidr = j / JPER;
        const int jj   = j - bidr * JPER;
        const int base = bidr * 56 + jj * 4 + g;
#pragma unroll
        for (int q = 0; q < 8; ++q) {
            int t = (bx << 7) + tx * 8 + q;
            d_G2[(size_t)t * GSTRIDE + base] = acc[ii][q] + bv;
        }
    }
}

// ---------------- persistent recurrent kernel --------------------------------
// 147 CTAs x 1024. kg = wid&7 (256-wide k slice), rg = wid>>3 (16 mma rows).
// Sync: per-CTA flags. Producer (warp 0) publishes flag[bid]=t+1 with
// st.release after h16 stores. Each warp polls ONLY its slice's ~20 producer
// CTAs, then computes immediately — producer spread overlaps with compute.
// Step barriers: S2 (before finalize) + S3 (sRed WAR).
__global__ void __launch_bounds__(1024, 1) lstm_recurrent(
    const float* __restrict__ Wf, const float* __restrict__ Wi,
    const float* __restrict__ Wc, const float* __restrict__ Wo,
    const float* __restrict__ Wy, const float* __restrict__ by,
    float* __restrict__ out)
{
    extern __shared__ char smem[];
    __half* sW   = (__half*)smem;
    float*  sRed = (float*)(smem + SRED_OFF);     // [kg][64]

    const int tid = threadIdx.x, wid = tid >> 5, lane = tid & 31;
    const int kg = wid & 7, rg = wid >> 3;
    const int bid = blockIdx.x, jb = bid * JPER;
    int njj = HID - jb; njj = njj < 0 ? 0 : (njj > JPER ? JPER : njj);
    float* out_y = out;
    float* out_h = out + (size_t)TSTEPS * NOUT;

    // producer range for this warp's k slice: j in [256*kg, 256*kg+255]
    int P0 = (256 * kg) / JPER;
    int P1 = (256 * kg + 255) / JPER;
    if (P1 > NCTA - 1) P1 = NCTA - 1;
    const unsigned* pollp = d_flags + (size_t)(P0 + lane) * FSTRIDE;
    const bool dopoll = (P0 + lane <= P1);
    unsigned* myflag = d_flags + (size_t)bid * FSTRIDE;

    // gate weights -> SMEM fp16 (56 rows x 2048 halfs, row stride SWS=2056)
    for (int c = tid; c < 56 * 256; c += 1024) {
        int gr = c >> 8;
        int k8 = (c & 255) << 3;
        int jj = gr >> 2, g = gr & 3;
        uint4 u = {0u, 0u, 0u, 0u};
        if (jj < njj) {
            const float* W = (g == 0) ? Wf : (g == 1) ? Wi : (g == 2) ? Wc : Wo;
            const float* p = W + (size_t)(jb + jj) * ZLEN + k8;
            float4 v0 = *(const float4*)p;
            float4 v1 = *(const float4*)(p + 4);
            u.x = packh2(v0.x, v0.y); u.y = packh2(v0.z, v0.w);
            u.z = packh2(v1.x, v1.y); u.w = packh2(v1.z, v1.w);
        }
        *(uint4*)(sW + gr * SWS + k8) = u;
    }

    // y-row weights -> registers (row bid*4 + rg), fp16, SAME permutation as h
    unsigned wy2[4] = {0u, 0u, 0u, 0u};
    if (bid < 128) {
        const float* prow = Wy + (size_t)(bid * 4 + rg) * HID;
#pragma unroll
        for (int c = 0; c < 4; ++c) {
            int i_c = kg * 128 + 32 * (lane >> 3) + 8 * c + (lane & 7);  // global h2 idx
            float2 v = *(const float2*)(prow + 2 * i_c);
            wy2[c] = packh2(v.x, v.y);
        }
    }

    // per-lane ldmatrix base address (shared-space u32), advances 32B per k-step
    unsigned sw_u = (unsigned)__cvta_generic_to_shared(sW);
    unsigned a_base;
    {
        int li = lane & 7, gsel = lane >> 3;
        int row_in_tile = ((gsel & 1) << 3) + li;
        if (rg == 3 && row_in_tile >= 8) row_in_tile -= 8;   // dup: only 8 real rows
        int k_half = (gsel >> 1) << 3;                        // 0 or 8
        a_base = sw_u + (unsigned)(((rg * 16 + row_in_tile) * SWS + kg * 256 + k_half) * 2);
    }

    float c_st = 0.0f;                       // warp 0, lane = jj
    float byv = 0.0f;
    if (wid == 0 && lane >= 16 && lane < 20 && bid < 128)
        byv = __ldg(by + bid * 4 + (lane - 16));
    __syncthreads();

    for (int t = 0; t <= TSTEPS; ++t) {
        // ---- per-warp wait: my slice's producers have published h(t-1) ----
        if (t > 0) {
            bool ok;
            do {
                ok = true;
                if (dopoll) {
                    unsigned v;
                    asm volatile("ld.acquire.gpu.global.u32 %0, [%1];"
                                 : "=r"(v) : "l"(pollp) : "memory");
                    ok = (v >= (unsigned)t);
                }
            } while (!__all_sync(0xFFFFFFFFu, ok));
        }

        // warp 0: prefetch this step's G early (long latency cover)
        float4 gv = {0.f, 0.f, 0.f, 0.f};
        if (wid == 0 && lane < JPER && t < TSTEPS)
            gv = __ldcg((const float4*)(d_G2 + (size_t)t * GSTRIDE + bid * 56 + lane * 4));

        // h(t-1) slice -> regs: one LDG.128 from permuted fp16 history
        unsigned hvc[4] = {0u, 0u, 0u, 0u};
        if (t > 0) {
            uint4 hv = __ldcg((const uint4*)(d_h16 + (size_t)(t - 1) * HID + kg * 256 + lane * 8));
            hvc[0] = hv.x; hvc[1] = hv.y; hvc[2] = hv.z; hvc[3] = hv.w;
        }

        // 16 k-steps of m16n8k16, two interleaved accumulators
        float cA0 = 0.f, cA1 = 0.f, cA2 = 0.f, cA3 = 0.f;
        float cB0 = 0.f, cB1 = 0.f, cB2 = 0.f, cB3 = 0.f;
        unsigned aaddr = a_base;
        const int q = lane & 3;
#pragma unroll
        for (int s = 0; s < 16; ++s) {
            unsigned a0, a1, a2, a3;
            ldmx4(a0, a1, a2, a3, aaddr);
            aaddr += 32;
            int srcb = q + 8 * (s >> 2);
            unsigned b0 = __shfl_sync(0xFFFFFFFFu, hvc[s & 3], srcb);
            unsigned b1 = __shfl_sync(0xFFFFFFFFu, hvc[s & 3], srcb + 4);
            if (s & 1) mma16816(cB0, cB1, cB2, cB3, a0, a1, a2, a3, b0, b1);
            else       mma16816(cA0, cA1, cA2, cA3, a0, a1, a2, a3, b0, b1);
        }
        cA0 += cB0; cA2 += cB2;                   // only col 0 needed (c0, c2)

        // y row: HFMA2 on permuted h regs + reduce
        float ysum;
        {
            __half2 acc = __hmul2(*(__half2*)&wy2[0], *(__half2*)&hvc[0]);
            acc = __hfma2(*(__half2*)&wy2[1], *(__half2*)&hvc[1], acc);
            acc = __hfma2(*(__half2*)&wy2[2], *(__half2*)&hvc[2], acc);
            acc = __hfma2(*(__half2*)&wy2[3], *(__half2*)&hvc[3], acc);
            float2 f = __half22float2(acc);
            ysum = f.x + f.y;
#pragma unroll
            for (int off = 16; off > 0; off >>= 1)
                ysum += __shfl_xor_sync(0xFFFFFFFFu, ysum, off);
        }

        // store gate partials (col 0 of D): lane&3==0 lanes hold rows
        if ((lane & 3) == 0) {
            int r0 = rg * 16 + (lane >> 2);
            sRed[kg * 64 + r0] = cA0;
            if (rg < 3) sRed[kg * 64 + r0 + 8] = cA2;
        }
        if (lane == 0) sRed[kg * 64 + 56 + rg] = ysum;

        __syncthreads();                          // S2: sRed complete

        if (wid == 0) {
            if (t < TSTEPS) {
                float hvout = 0.0f;
                const bool act = (lane < njj);
                if (act) {
                    float4 a = *(const float4*)(sRed + 0 * 64 + lane * 4);
#pragma unroll
                    for (int k2 = 1; k2 < 8; ++k2) {
                        float4 b = *(const float4*)(sRed + k2 * 64 + lane * 4);
                        a.x += b.x; a.y += b.y; a.z += b.z; a.w += b.w;
                    }
                    a.x += gv.x; a.y += gv.y; a.z += gv.z; a.w += gv.w;
                    float fg = sigmoidf_(a.x);
                    float ig = sigmoidf_(a.y);
                    float cc = tanhf_(a.z);
                    float og = sigmoidf_(a.w);
                    c_st = fg * c_st + ig * cc;
                    hvout = og * tanhf_(c_st);
                    int j  = jb + lane;
                    int sl = j >> 8;
                    int l  = j & 255;
                    int ip = hperm(l >> 1);
                    d_h16[(size_t)t * HID + sl * 256 + ip * 2 + (l & 1)] = __float2half(hvout);
                }
                __syncwarp();                     // order lane stores before publish
                if (lane == 0)
                    asm volatile("st.release.gpu.global.u32 [%0], %1;"
                                 :: "l"(myflag), "r"((unsigned)(t + 1)) : "memory");
                if (act)
                    out_h[(size_t)t * HID + jb + lane] = hvout;   // fp32 output, off-path
            }
            // y output off the critical path (after publish)
            if (t >= 1 && bid < 128 && lane >= 16 && lane < 20) {
                float s = 0.0f;
#pragma unroll
                for (int k2 = 0; k2 < 8; ++k2) s += sRed[k2 * 64 + 56 + (lane - 16)];
                out_y[(size_t)(t - 1) * NOUT + bid * 4 + (lane - 16)] = s + byv;
            }
        }
        __syncthreads();                          // S3: sRed WAR protection
    }
}

extern "C" void kernel_launch(void* const* d_in, const int* in_sizes, int n_in,
                              void* d_out, int out_size) {
    (void)in_sizes; (void)n_in; (void)out_size;
    const float* X  = (const float*)d_in[0];
    const float* Wf = (const float*)d_in[1];
    const float* bf = (const float*)d_in[2];
    const float* Wi = (const float*)d_in[3];
    const float* bi = (const float*)d_in[4];
    const float* Wc = (const float*)d_in[5];
    const float* bc = (const float*)d_in[6];
    const float* Wo = (const float*)d_in[7];
    const float* bo = (const float*)d_in[8];
    const float* Wy = (const float*)d_in[9];
    const float* by = (const float*)d_in[10];
    float* out = (float*)d_out;

    cudaFuncSetAttribute(lstm_recurrent,
                         cudaFuncAttributeMaxDynamicSharedMemorySize, SMEM_TOTAL);
    void* flagp = nullptr;
    cudaGetSymbolAddress(&flagp, d_flags);
    cudaMemsetAsync(flagp, 0, NCTA * FSTRIDE * sizeof(unsigned), 0);

    gemm_xpart<<<dim3(16, 64), 256>>>(Wf, Wi, Wc, Wo, bf, bi, bc, bo, X);
    lstm_recurrent<<<NCTA, 1024, SMEM_TOTAL>>>(Wf, Wi, Wc, Wo, Wy, by, out);
}

// round 17
// speedup vs baseline: 1.0139x; 1.0139x over previous
#include <cuda_runtime.h>
#include <cuda_fp16.h>

#define TSTEPS 2048
#define HID    2048
#define INP    1024
#define NOUT   512
#define ZLEN   (HID + INP)
#define NCTA   147
#define JPER   14
#define GSTRIDE (NCTA * 56)                  /* 8232 floats per timestep */
#define SWS    2056                          /* padded row stride (halfs): conflict-free ldmatrix */
#define NREP   8                             /* h replica count (L2 hotspot spread) */

#define SRED_OFF   (56 * SWS * 2)            /* 230272 : sRed[8][64] f32 */
#define SMEM_TOTAL (SRED_OFF + 2048)         /* 232320 <= 232448 */

__device__ __align__(256) float  d_G2[(size_t)TSTEPS * GSTRIDE];
__device__ __align__(256) __half d_h16[(size_t)TSTEPS * NREP * HID]; /* PERMUTED, 8 replicas */
__device__ unsigned d_bar;

__device__ __forceinline__ unsigned packh2(float a, float b) {
    __half2 h = __floats2half2_rn(a, b);
    return *(unsigned*)&h;
}
__device__ __forceinline__ float sigmoidf_(float x) { return 1.0f / (1.0f + __expf(-x)); }
__device__ __forceinline__ float tanhf_(float x) {
    float e = __expf(2.0f * x); return 1.0f - 2.0f / (e + 1.0f);
}
__device__ __forceinline__ void ldmx4(unsigned &r0, unsigned &r1, unsigned &r2, unsigned &r3,
                                      unsigned addr) {
    asm volatile("ldmatrix.sync.aligned.m8n8.x4.shared.b16 {%0,%1,%2,%3}, [%4];"
                 : "=r"(r0), "=r"(r1), "=r"(r2), "=r"(r3) : "r"(addr));
}
__device__ __forceinline__ void mma16816(float &c0, float &c1, float &c2, float &c3,
                                         unsigned a0, unsigned a1, unsigned a2, unsigned a3,
                                         unsigned b0, unsigned b1) {
    asm volatile("mma.sync.aligned.m16n8k16.row.col.f32.f16.f16.f32 "
                 "{%0,%1,%2,%3}, {%4,%5,%6,%7}, {%8,%9}, {%0,%1,%2,%3};"
                 : "+f"(c0), "+f"(c1), "+f"(c2), "+f"(c3)
                 : "r"(a0), "r"(a1), "r"(a2), "r"(a3), "r"(b0), "r"(b1));
}

// h-exchange permutation within a 256-half slice (see R15 derivation).
__device__ __forceinline__ int hperm(int i) {
    return 4 * ((i & 7) + 8 * (i >> 5)) + ((i >> 3) & 3);
}

// ---------------- GEMM: x-part preactivations, transposed output layout -------
__global__ __launch_bounds__(256) void gemm_xpart(
    const float* __restrict__ Wf, const float* __restrict__ Wi,
    const float* __restrict__ Wc, const float* __restrict__ Wo,
    const float* __restrict__ bf, const float* __restrict__ bi,
    const float* __restrict__ bc, const float* __restrict__ bo,
    const float* __restrict__ X)
{
    __shared__ float As[16][132];
    __shared__ float Bs[16][132];
    const int bx = blockIdx.x, by = blockIdx.y;
    const int g = by >> 4, jb2 = (by & 15) << 7;
    const float* W  = (g == 0) ? Wf : (g == 1) ? Wi : (g == 2) ? Wc : Wo;
    const float* bb = (g == 0) ? bf : (g == 1) ? bi : (g == 2) ? bc : bo;
    const int tid = threadIdx.x, tx = tid & 15, ty = tid >> 4;
    float acc[8][8];
#pragma unroll
    for (int i = 0; i < 8; ++i)
#pragma unroll
        for (int j = 0; j < 8; ++j) acc[i][j] = 0.0f;
    for (int k0 = 0; k0 < INP; k0 += 16) {
#pragma unroll
        for (int i = 0; i < 2; ++i) {
            int f = tid + i * 256, row = f >> 2, kk = (f & 3) << 2;
            float4 v = *(const float4*)(W + (size_t)(jb2 + row) * ZLEN + HID + k0 + kk);
            As[kk][row] = v.x; As[kk+1][row] = v.y; As[kk+2][row] = v.z; As[kk+3][row] = v.w;
            float4 u = *(const float4*)(X + (size_t)((bx << 7) + row) * INP + k0 + kk);
            Bs[kk][row] = u.x; Bs[kk+1][row] = u.y; Bs[kk+2][row] = u.z; Bs[kk+3][row] = u.w;
        }
        __syncthreads();
#pragma unroll
        for (int k = 0; k < 16; ++k) {
            float a[8], b[8];
            *(float4*)&a[0] = *(const float4*)&As[k][ty*8];
            *(float4*)&a[4] = *(const float4*)&As[k][ty*8+4];
            *(float4*)&b[0] = *(const float4*)&Bs[k][tx*8];
            *(float4*)&b[4] = *(const float4*)&Bs[k][tx*8+4];
#pragma unroll
            for (int ii = 0; ii < 8; ++ii)
#pragma unroll
                for (int jj = 0; jj < 8; ++jj)
                    acc[ii][jj] = fmaf(a[ii], b[jj], acc[ii][jj]);
        }
        __syncthreads();
    }
#pragma unroll
    for (int ii = 0; ii < 8; ++ii) {
        const int j = jb2 + ty * 8 + ii;
        const float bv = __ldg(bb + j);
        const int bidr = j / JPER;
        const int jj   = j - bidr * JPER;
        const int base = bidr * 56 + jj * 4 + g;
#pragma unroll
        for (int q = 0; q < 8; ++q) {
            int t = (bx << 7) + tx * 8 + q;
            d_G2[(size_t)t * GSTRIDE + base] = acc[ii][q] + bv;
        }
    }
}

// ---------------- persistent recurrent kernel --------------------------------
// 147 CTAs x 1024. kg = wid&7 (256-wide k slice), rg = wid>>3 (16 mma rows).
// R15 structure (counter barrier, single poller, MMA engine, permuted h) +
// NREP=8 replicated h-exchange buffers: producer stores h to all replicas,
// consumer warp reads replica (bid+wid)&7 -> spreads the per-step 4KB L2
// hotspot over 32KB / many LTS partitions.
__global__ void __launch_bounds__(1024, 1) lstm_recurrent(
    const float* __restrict__ Wf, const float* __restrict__ Wi,
    const float* __restrict__ Wc, const float* __restrict__ Wo,
    const float* __restrict__ Wy, const float* __restrict__ by,
    float* __restrict__ out)
{
    extern __shared__ char smem[];
    __half* sW   = (__half*)smem;
    float*  sRed = (float*)(smem + SRED_OFF);     // [kg][64]

    const int tid = threadIdx.x, wid = tid >> 5, lane = tid & 31;
    const int kg = wid & 7, rg = wid >> 3;
    const int bid = blockIdx.x, jb = bid * JPER;
    int njj = HID - jb; njj = njj < 0 ? 0 : (njj > JPER ? JPER : njj);
    float* out_y = out;
    float* out_h = out + (size_t)TSTEPS * NOUT;
    unsigned* barp = &d_bar;
    const int rep = (bid + wid) & (NREP - 1);

    // gate weights -> SMEM fp16 (56 rows x 2048 halfs, row stride SWS=2056)
    for (int c = tid; c < 56 * 256; c += 1024) {
        int gr = c >> 8;
        int k8 = (c & 255) << 3;
        int jj = gr >> 2, g = gr & 3;
        uint4 u = {0u, 0u, 0u, 0u};
        if (jj < njj) {
            const float* W = (g == 0) ? Wf : (g == 1) ? Wi : (g == 2) ? Wc : Wo;
            const float* p = W + (size_t)(jb + jj) * ZLEN + k8;
            float4 v0 = *(const float4*)p;
            float4 v1 = *(const float4*)(p + 4);
            u.x = packh2(v0.x, v0.y); u.y = packh2(v0.z, v0.w);
            u.z = packh2(v1.x, v1.y); u.w = packh2(v1.z, v1.w);
        }
        *(uint4*)(sW + gr * SWS + k8) = u;
    }

    // y-row weights -> registers (row bid*4 + rg), fp16, SAME permutation as h
    unsigned wy2[4] = {0u, 0u, 0u, 0u};
    if (bid < 128) {
        const float* prow = Wy + (size_t)(bid * 4 + rg) * HID;
#pragma unroll
        for (int c = 0; c < 4; ++c) {
            int i_c = kg * 128 + 32 * (lane >> 3) + 8 * c + (lane & 7);  // global h2 idx
            float2 v = *(const float2*)(prow + 2 * i_c);
            wy2[c] = packh2(v.x, v.y);
        }
    }

    // per-lane ldmatrix base address (shared-space u32), advances 32B per k-step
    unsigned sw_u = (unsigned)__cvta_generic_to_shared(sW);
    unsigned a_base;
    {
        int li = lane & 7, gsel = lane >> 3;
        int row_in_tile = ((gsel & 1) << 3) + li;
        if (rg == 3 && row_in_tile >= 8) row_in_tile -= 8;   // dup: only 8 real rows
        int k_half = (gsel >> 1) << 3;                        // 0 or 8
        a_base = sw_u + (unsigned)(((rg * 16 + row_in_tile) * SWS + kg * 256 + k_half) * 2);
    }

    float c_st = 0.0f;                       // warp 0, lane = jj
    float byv = 0.0f;
    if (wid == 0 && lane >= 16 && lane < 20 && bid < 128)
        byv = __ldg(by + bid * 4 + (lane - 16));

    for (int t = 0; t <= TSTEPS; ++t) {
        if (t > 0 && wid == 0 && lane == 0) {     // single poller per CTA
            const unsigned target = (unsigned)t * (unsigned)NCTA;
            unsigned v;
            do {
                asm volatile("ld.acquire.gpu.global.u32 %0, [%1];"
                             : "=r"(v) : "l"(barp) : "memory");
            } while (v < target);
        }
        __syncthreads();                          // S1: release CTA; orders sRed WAR

        // warp 0: prefetch this step's G early (long latency cover)
        float4 gv = {0.f, 0.f, 0.f, 0.f};
        if (wid == 0 && lane < JPER && t < TSTEPS)
            gv = __ldcg((const float4*)(d_G2 + (size_t)t * GSTRIDE + bid * 56 + lane * 4));

        // h(t-1) slice -> regs: one LDG.128 from this warp's replica
        unsigned hvc[4] = {0u, 0u, 0u, 0u};
        if (t > 0) {
            uint4 hv = __ldcg((const uint4*)(d_h16
                + ((size_t)(t - 1) * NREP + rep) * HID + kg * 256 + lane * 8));
            hvc[0] = hv.x; hvc[1] = hv.y; hvc[2] = hv.z; hvc[3] = hv.w;
        }

        // 16 k-steps of m16n8k16, two interleaved accumulators
        float cA0 = 0.f, cA1 = 0.f, cA2 = 0.f, cA3 = 0.f;
        float cB0 = 0.f, cB1 = 0.f, cB2 = 0.f, cB3 = 0.f;
        unsigned aaddr = a_base;
        const int q = lane & 3;
#pragma unroll
        for (int s = 0; s < 16; ++s) {
            unsigned a0, a1, a2, a3;
            ldmx4(a0, a1, a2, a3, aaddr);
            aaddr += 32;
            int srcb = q + 8 * (s >> 2);
            unsigned b0 = __shfl_sync(0xFFFFFFFFu, hvc[s & 3], srcb);
            unsigned b1 = __shfl_sync(0xFFFFFFFFu, hvc[s & 3], srcb + 4);
            if (s & 1) mma16816(cB0, cB1, cB2, cB3, a0, a1, a2, a3, b0, b1);
            else       mma16816(cA0, cA1, cA2, cA3, a0, a1, a2, a3, b0, b1);
        }
        cA0 += cB0; cA2 += cB2;                   // only col 0 needed (c0, c2)

        // y row: HFMA2 on permuted h regs + reduce
        float ysum;
        {
            __half2 acc = __hmul2(*(__half2*)&wy2[0], *(__half2*)&hvc[0]);
            acc = __hfma2(*(__half2*)&wy2[1], *(__half2*)&hvc[1], acc);
            acc = __hfma2(*(__half2*)&wy2[2], *(__half2*)&hvc[2], acc);
            acc = __hfma2(*(__half2*)&wy2[3], *(__half2*)&hvc[3], acc);
            float2 f = __half22float2(acc);
            ysum = f.x + f.y;
#pragma unroll
            for (int off = 16; off > 0; off >>= 1)
                ysum += __shfl_xor_sync(0xFFFFFFFFu, ysum, off);
        }

        // store gate partials (col 0 of D): lane&3==0 lanes hold rows
        if ((lane & 3) == 0) {
            int r0 = rg * 16 + (lane >> 2);
            sRed[kg * 64 + r0] = cA0;
            if (rg < 3) sRed[kg * 64 + r0 + 8] = cA2;
        }
        if (lane == 0) sRed[kg * 64 + 56 + rg] = ysum;

        __syncthreads();                          // S2

        if (wid == 0) {
            if (t < TSTEPS) {
                float hvout = 0.0f;
                const bool act = (lane < njj);
                if (act) {
                    float4 a = *(const float4*)(sRed + 0 * 64 + lane * 4);
#pragma unroll
                    for (int k2 = 1; k2 < 8; ++k2) {
                        float4 b = *(const float4*)(sRed + k2 * 64 + lane * 4);
                        a.x += b.x; a.y += b.y; a.z += b.z; a.w += b.w;
                    }
                    a.x += gv.x; a.y += gv.y; a.z += gv.z; a.w += gv.w;
                    float fg = sigmoidf_(a.x);
                    float ig = sigmoidf_(a.y);
                    float cc = tanhf_(a.z);
                    float og = sigmoidf_(a.w);
                    c_st = fg * c_st + ig * cc;
                    hvout = og * tanhf_(c_st);
                    // exchange store, PERMUTED layout, ALL replicas
                    int j  = jb + lane;
                    int sl = j >> 8;
                    int l  = j & 255;
                    int ip = hperm(l >> 1);
                    __half h16v = __float2half(hvout);
                    size_t off = (size_t)sl * 256 + ip * 2 + (l & 1);
#pragma unroll
                    for (int r = 0; r < NREP; ++r)
                        d_h16[((size_t)t * NREP + r) * HID + off] = h16v;
                }
                __syncwarp();                     // order lane stores before release
                if (lane == 0)                    // ONE arrival per CTA
                    asm volatile("red.release.gpu.global.add.u32 [%0], %1;"
                                 :: "l"(barp), "r"(1u) : "memory");
                if (act)
                    out_h[(size_t)t * HID + jb + lane] = hvout;   // fp32 output, off-path
            }
            // y output off the critical path (after publish)
            if (t >= 1 && bid < 128 && lane >= 16 && lane < 20) {
                float s = 0.0f;
#pragma unroll
                for (int k2 = 0; k2 < 8; ++k2) s += sRed[k2 * 64 + 56 + (lane - 16)];
                out_y[(size_t)(t - 1) * NOUT + bid * 4 + (lane - 16)] = s + byv;
            }
        }
    }
}

extern "C" void kernel_launch(void* const* d_in, const int* in_sizes, int n_in,
                              void* d_out, int out_size) {
    (void)in_sizes; (void)n_in; (void)out_size;
    const float* X  = (const float*)d_in[0];
    const float* Wf = (const float*)d_in[1];
    const float* bf = (const float*)d_in[2];
    const float* Wi = (const float*)d_in[3];
    const float* bi = (const float*)d_in[4];
    const float* Wc = (const float*)d_in[5];
    const float* bc = (const float*)d_in[6];
    const float* Wo = (const float*)d_in[7];
    const float* bo = (const float*)d_in[8];
    const float* Wy = (const float*)d_in[9];
    const float* by = (const float*)d_in[10];
    float* out = (float*)d_out;

    cudaFuncSetAttribute(lstm_recurrent,
                         cudaFuncAttributeMaxDynamicSharedMemorySize, SMEM_TOTAL);
    void* barp = nullptr;
    cudaGetSymbolAddress(&barp, d_bar);
    cudaMemsetAsync(barp, 0, sizeof(unsigned), 0);

    gemm_xpart<<<dim3(16, 64), 256>>>(Wf, Wi, Wc, Wo, bf, bi, bc, bo, X);
    lstm_recurrent<<<NCTA, 1024, SMEM_TOTAL>>>(Wf, Wi, Wc, Wo, Wy, by, out);
}